// round 7
// baseline (speedup 1.0000x reference)
#include <cuda_runtime.h>
#include <math.h>

#define NB     32
#define NPG1   256
#define NFEATD 128
#define NHID   64
#define KP1    128
#define KP2    64
#define NN1    (NB*NPG1)   // 8192
#define NN2    (NB*KP1)    // 4096
#define NN3    (NB*KP2)    // 2048
#define NCLS   6
#define PROJ_MAX 0.996f
#define MINN   1e-15f
#define AART   3.1063030f   // artanh(0.996)

// ---------------- device scratch ----------------
__device__ unsigned g_bm[NN1*8];        // layer-1 adjacency bitmap; ALWAYS zero at kernel_launch entry
__device__ float g_s[NN1];
__device__ float g_u[NN1*NHID];
__device__ float g_t1[NN1*NHID];
__device__ float g_dis[NN1];
__device__ float g_score[NN1];
__device__ float g_xn1[NN2*NHID];
__device__ float g_adj2[NB*KP1*KP1];
__device__ float g_t2[NN2*NHID];
__device__ float g_xn2[NN3*NHID];
__device__ float g_adj3[NB*KP2*KP2];
__device__ float g_t3[NN3*NHID];

// ---------------- helpers ----------------
__device__ __forceinline__ float artanh_(float x){
    x = fminf(fmaxf(x, -1.0f + 1e-7f), 1.0f - 1e-7f);
    return 0.5f*(log1pf(x) - log1pf(-x));
}
__device__ __forceinline__ float warpSum(float v){
    #pragma unroll
    for (int o = 16; o; o >>= 1) v += __shfl_xor_sync(0xffffffffu, v, o);
    return v;
}

// mobius tail: u = logmap0(proj(mobius_add(proj(expmap-scaled matvec), hb)))
__device__ __forceinline__ void hyp_tail(float mx0, float mx1, float xn,
                                         const float* __restrict__ bb, int l,
                                         float* __restrict__ up){
    float mxn = fmaxf(sqrtf(warpSum(mx0*mx0 + mx1*mx1)), MINN);
    float tv  = tanhf(mxn/xn*artanh_(xn));
    float hs  = tv/mxn;
    float h0 = mx0*hs, h1 = mx1*hs;
    float hn = tv;
    if (hn > PROJ_MAX){ float c = PROJ_MAX/hn; h0 *= c; h1 *= c; hn = PROJ_MAX; }
    float x2 = hn*hn;
    float b0 = bb[l], b1 = bb[l+32];
    float bn = fmaxf(sqrtf(warpSum(b0*b0 + b1*b1)), MINN);
    float tb = tanhf(bn);
    float hbs = tb/bn, hbn = tb;
    if (tb > PROJ_MAX){ hbs = PROJ_MAX/bn; hbn = PROJ_MAX; }
    float hb0 = b0*hbs, hb1 = b1*hbs;
    float y2 = hbn*hbn;
    float xy = warpSum(h0*hb0 + h1*hb1);
    float ca = 1.f + 2.f*xy + y2, cb = 1.f - x2;
    float den = fmaxf(1.f + 2.f*xy + x2*y2, MINN);
    float r0 = (ca*h0 + cb*hb0)/den, r1 = (ca*h1 + cb*hb1)/den;
    float rn = fmaxf(sqrtf(warpSum(r0*r0 + r1*r1)), MINN);
    float pn = rn, psc = 1.f;
    if (rn > PROJ_MAX){ psc = PROJ_MAX/rn; pn = PROJ_MAX; }
    float ls = artanh_(pn)/pn*psc;
    up[l] = r0*ls; up[l+32] = r1*ls;
}

__device__ __forceinline__ void agg_epi(int node, float a0, float a1, float deg,
                                        float* __restrict__ tout, float* __restrict__ dis, int l){
    float n1 = sqrtf(warpSum(a0*a0 + a1*a1));
    float s1 = (n1 > AART) ? AART/n1 : 1.f;
    float w0 = fmaxf(a0*s1, 0.f), w1 = fmaxf(a1*s1, 0.f);
    float n2 = sqrtf(warpSum(w0*w0 + w1*w1));
    float s2 = (n2 > AART) ? AART/n2 : 1.f;
    tout[(size_t)node*64 + l]      = w0*s2;
    tout[(size_t)node*64 + l + 32] = w1*s2;
    if (l == 0) dis[node] = (deg > 0.f) ? rsqrtf(deg) : 0.f;
}

// ---------------- K1: edge scatter + row sums + to_hyp + HypLinear (layer1) ----------------
// bitmap is guaranteed zero at entry (zeroed by k_topk1 tail of the previous run,
// and device globals are zero-initialized on first run).
__global__ void k_prep1(const float* __restrict__ x, const float* __restrict__ W1,
                        const float* __restrict__ bb, const int* __restrict__ ei, int E,
                        unsigned* __restrict__ bm, float* __restrict__ s, float* __restrict__ u){
    __shared__ float Wt[128*64];
    int tid = threadIdx.x;
    // scatter a slice of edges into the bitmap (atomicOr; dedup for free)
    for (int e = blockIdx.x*256 + tid; e < E; e += 1024*256){
        int r = ei[e], c = ei[E + e];
        int lc = c & 255;
        atomicOr(&bm[(size_t)r*8 + (lc >> 5)], 1u << (lc & 31));
    }
    for (int e = tid; e < 128*64; e += 256){
        int j = e >> 7, k = e & 127;
        Wt[k*64 + j] = W1[e];
    }
    __syncthreads();
    int w = tid >> 5, l = tid & 31;
    int node = blockIdx.x*8 + w;
    const float* xp = x + (size_t)node*128;
    float xq[4];
    #pragma unroll
    for (int q = 0; q < 4; q++) xq[q] = xp[l + 32*q];
    float ssum = warpSum(xq[0]+xq[1]+xq[2]+xq[3]);
    if (l == 0) s[node] = ssum;
    float n0 = fmaxf(sqrtf(warpSum(xq[0]*xq[0]+xq[1]*xq[1]+xq[2]*xq[2]+xq[3]*xq[3])), MINN);
    float th = tanhf(n0);
    float xsc, xn;
    if (th > PROJ_MAX){ xsc = PROJ_MAX/n0; xn = PROJ_MAX; } else { xsc = th/n0; xn = th; }
    xn = fmaxf(xn, MINN);
    #pragma unroll
    for (int q = 0; q < 4; q++) xq[q] *= xsc;
    float mx0 = 0.f, mx1 = 0.f;
    #pragma unroll
    for (int q = 0; q < 4; q++){
        float xv = xq[q];
        for (int kk = 0; kk < 32; kk++){
            float xk = __shfl_sync(0xffffffffu, xv, kk);
            int k = q*32 + kk;
            mx0 += xk*Wt[k*64 + l];
            mx1 += xk*Wt[k*64 + l + 32];
        }
    }
    hyp_tail(mx0, mx1, xn, bb, l, u + (size_t)node*64);
}

// ---------------- K3: sparse layer-1 HypAgg, batched gathers (MLP=8) ----------------
__global__ void k_agg1(const unsigned* __restrict__ bm, const float* __restrict__ s,
                       const float* __restrict__ u, float* __restrict__ tout,
                       float* __restrict__ dis){
    int w = threadIdx.x >> 5, l = threadIdx.x & 31;
    int node = blockIdx.x*8 + w;
    int g = node >> 8;
    const float* ug = u + ((size_t)(g << 8))*64;
    const float* sg = s + (g << 8);
    float sn = sg[node & 255];
    size_t idx = (size_t)node*8;
    unsigned bits = bm[idx]; int w8 = 0;
    float a0 = 0.f, a1 = 0.f, deg = 0.f;
    bool more = true;
    while (more){
        int cols[8];
        #pragma unroll
        for (int m = 0; m < 8; m++){
            while (bits == 0 && w8 < 7){ w8++; bits = bm[idx + w8]; }
            if (bits){ int b = __ffs(bits) - 1; bits &= bits - 1; cols[m] = (w8 << 5) | b; }
            else cols[m] = -1;
        }
        more = (bits != 0) || (w8 < 7);
        float wv[8], u0[8], u1[8];
        #pragma unroll
        for (int m = 0; m < 8; m++){
            int c = cols[m] < 0 ? 0 : cols[m];
            wv[m] = cols[m] < 0 ? 0.f : 0.5f*(sn + sg[c]);
            u0[m] = ug[(size_t)c*64 + l];
            u1[m] = ug[(size_t)c*64 + l + 32];
        }
        #pragma unroll
        for (int m = 0; m < 8; m++){
            a0 += wv[m]*u0[m]; a1 += wv[m]*u1[m]; deg += wv[m];
        }
    }
    agg_epi(node, a0, a1, deg, tout, dis, l);
}

// ---------------- K4: sparse layer-1 node information score, batched ----------------
__global__ void k_score1(const unsigned* __restrict__ bm, const float* __restrict__ s,
                         const float* __restrict__ t, const float* __restrict__ dis,
                         float* __restrict__ score){
    int w = threadIdx.x >> 5, l = threadIdx.x & 31;
    int node = blockIdx.x*8 + w;
    int g = node >> 8;
    const float* tg = t + ((size_t)(g << 8))*64;
    const float* sg = s + (g << 8);
    const float* dg = dis + (g << 8);
    float sn = sg[node & 255];
    float dn = dg[node & 255];
    size_t idx = (size_t)node*8;
    unsigned bits = bm[idx]; int w8 = 0;
    float a0 = 0.f, a1 = 0.f;
    bool more = true;
    while (more){
        int cols[8];
        #pragma unroll
        for (int m = 0; m < 8; m++){
            while (bits == 0 && w8 < 7){ w8++; bits = bm[idx + w8]; }
            if (bits){ int b = __ffs(bits) - 1; bits &= bits - 1; cols[m] = (w8 << 5) | b; }
            else cols[m] = -1;
        }
        more = (bits != 0) || (w8 < 7);
        float wv[8], u0[8], u1[8];
        #pragma unroll
        for (int m = 0; m < 8; m++){
            int c = cols[m] < 0 ? 0 : cols[m];
            wv[m] = cols[m] < 0 ? 0.f : 0.5f*(sn + sg[c])*dg[c];
            u0[m] = tg[(size_t)c*64 + l];
            u1[m] = tg[(size_t)c*64 + l + 32];
        }
        #pragma unroll
        for (int m = 0; m < 8; m++){
            a0 += wv[m]*u0[m]; a1 += wv[m]*u1[m];
        }
    }
    float tr0 = tg[(size_t)(node & 255)*64 + l];
    float tr1 = tg[(size_t)(node & 255)*64 + l + 32];
    float d = fabsf(tr0 - dn*a0) + fabsf(tr1 - dn*a1);
    float sc = warpSum(d);
    if (l == 0) score[node] = sc;
}

// ---------------- K5a: layer-1 top-k + xn + att dots + adj2 build + bitmap reset ----------------
__global__ void k_topk1(const float* __restrict__ score, const float* __restrict__ tin,
                        const float* __restrict__ att, unsigned* __restrict__ bm,
                        const float* __restrict__ s,
                        float* __restrict__ xn, float* __restrict__ adj2){
    __shared__ float key[256];
    __shared__ int   idx[256];
    __shared__ float sa1[128], sa2[128], ss[256], satt[128];
    __shared__ int   sli[128];
    int g = blockIdx.x, t = threadIdx.x;          // 256 threads
    key[t] = score[g*256 + t]; idx[t] = t; ss[t] = s[g*256 + t];
    if (t < 128) satt[t] = att[t];
    for (int size = 2; size <= 256; size <<= 1){
        for (int stride = size >> 1; stride > 0; stride >>= 1){
            __syncthreads();
            int p = t ^ stride;
            if (p > t){
                float ka = key[t], kb = key[p];
                int ia = idx[t], ib = idx[p];
                bool before = (ka > kb) || (ka == kb && ia < ib);
                bool desc = ((t & size) == 0);
                if (desc ? !before : before){
                    key[t] = kb; key[p] = ka; idx[t] = ib; idx[p] = ia;
                }
            }
        }
    }
    __syncthreads();
    if (t < 128){
        int li = idx[t]; sli[t] = li;
        float tv = tanhf(key[t]);
        const float* src = tin + ((size_t)g*256 + li)*64;
        float* dst = xn + ((size_t)g*128 + t)*64;
        float d1 = 0.f, d2 = 0.f;
        #pragma unroll 8
        for (int j = 0; j < 64; j++){
            float v = src[j]*tv; dst[j] = v;
            d1 += v*satt[j]; d2 += v*satt[64 + j];
        }
        sa1[t] = d1; sa2[t] = d2;
    }
    __syncthreads();
    unsigned* bmg = bm + (size_t)g*256*8;
    for (int e = t; e < 128*128; e += 256){
        int i = e >> 7, j = e & 127;
        float ev = fmaxf(sa1[i] + sa2[j], 0.f);   // relu(leaky_relu(e)) == relu(e)
        int li = sli[i], lj = sli[j];
        unsigned word = bmg[li*8 + (lj >> 5)];
        float old = ((word >> (lj & 31)) & 1u) ? 0.5f*(ss[li] + ss[lj]) : 0.f;
        adj2[((size_t)g*128 + i)*128 + j] = ev + old;
    }
    __syncthreads();                               // all bitmap reads done
    {   // reset this graph's bitmap slice for the next kernel_launch invocation
        uint4 z = make_uint4(0u,0u,0u,0u);
        uint4* pz = (uint4*)bmg;                    // 2048 words = 512 uint4
        pz[t] = z; pz[t + 256] = z;
    }
}

// ---------------- K5b: layer-2 top-k + adj3 build (dense oldadj) ----------------
__global__ void k_topk2(const float* __restrict__ score, const float* __restrict__ tin,
                        const float* __restrict__ att, const float* __restrict__ oldadj,
                        float* __restrict__ xn, float* __restrict__ adj3){
    __shared__ float key[128];
    __shared__ int   idx[128];
    __shared__ float sa1[64], sa2[64], satt[128];
    __shared__ int   sli[64];
    int g = blockIdx.x, t = threadIdx.x;          // 128 threads
    key[t] = score[g*128 + t]; idx[t] = t; satt[t] = att[t];
    for (int size = 2; size <= 128; size <<= 1){
        for (int stride = size >> 1; stride > 0; stride >>= 1){
            __syncthreads();
            int p = t ^ stride;
            if (p > t){
                float ka = key[t], kb = key[p];
                int ia = idx[t], ib = idx[p];
                bool before = (ka > kb) || (ka == kb && ia < ib);
                bool desc = ((t & size) == 0);
                if (desc ? !before : before){
                    key[t] = kb; key[p] = ka; idx[t] = ib; idx[p] = ia;
                }
            }
        }
    }
    __syncthreads();
    if (t < 64){
        int li = idx[t]; sli[t] = li;
        float tv = tanhf(key[t]);
        const float* src = tin + ((size_t)g*128 + li)*64;
        float* dst = xn + ((size_t)g*64 + t)*64;
        float d1 = 0.f, d2 = 0.f;
        #pragma unroll 8
        for (int j = 0; j < 64; j++){
            float v = src[j]*tv; dst[j] = v;
            d1 += v*satt[j]; d2 += v*satt[64 + j];
        }
        sa1[t] = d1; sa2[t] = d2;
    }
    __syncthreads();
    const float* oag = oldadj + (size_t)g*128*128;
    for (int e = t; e < 64*64; e += 128){
        int i = e >> 6, j = e & 63;
        float ev = fmaxf(sa1[i] + sa2[j], 0.f);
        adj3[((size_t)g*64 + i)*64 + j] = ev + oag[(size_t)sli[i]*128 + sli[j]];
    }
}

// ---------------- K7: to_hyp + HypLinear, 64-dim ----------------
__global__ void k_linear(const float* __restrict__ xin, const float* __restrict__ W,
                         const float* __restrict__ bb, float* __restrict__ u){
    __shared__ float Wt[64*64];
    int tid = threadIdx.x;
    for (int e = tid; e < 4096; e += 256){
        int j = e >> 6, k = e & 63;
        Wt[k*64 + j] = W[e];
    }
    __syncthreads();
    int w = tid >> 5, l = tid & 31;
    int node = blockIdx.x*8 + w;
    const float* xp = xin + (size_t)node*64;
    float x0 = xp[l], x1 = xp[l+32];
    float n0 = fmaxf(sqrtf(warpSum(x0*x0 + x1*x1)), MINN);
    float th = tanhf(n0);
    float xsc, xn;
    if (th > PROJ_MAX){ xsc = PROJ_MAX/n0; xn = PROJ_MAX; } else { xsc = th/n0; xn = th; }
    xn = fmaxf(xn, MINN);
    x0 *= xsc; x1 *= xsc;
    float mx0 = 0.f, mx1 = 0.f;
    #pragma unroll
    for (int q = 0; q < 2; q++){
        float xv = q ? x1 : x0;
        for (int kk = 0; kk < 32; kk++){
            float xk = __shfl_sync(0xffffffffu, xv, kk);
            int k = q*32 + kk;
            mx0 += xk*Wt[k*64 + l];
            mx1 += xk*Wt[k*64 + l + 32];
        }
    }
    hyp_tail(mx0, mx1, xn, bb, l, u + (size_t)node*64);
}

// ---------------- dense HypAgg, 2 rows/warp ----------------
template<int NPG>
__global__ void k_aggT(const float* __restrict__ adj, const float* __restrict__ u,
                       float* __restrict__ tout, float* __restrict__ dis){
    constexpr int TPG = NPG/16;
    __shared__ float ush[NPG*64];
    int g = blockIdx.x / TPG, rt = blockIdx.x % TPG;
    int w = threadIdx.x >> 5, l = threadIdx.x & 31;
    int rbase = rt*16 + w*2;
    const float* adjg = adj + (size_t)g*NPG*NPG;
    const float* ug   = u   + (size_t)g*NPG*64;
    {
        const float4* src = (const float4*)ug;
        float4* dst = (float4*)ush;
        for (int e = threadIdx.x; e < NPG*16; e += 256) dst[e] = src[e];
    }
    __syncthreads();
    const float* r0p = adjg + (size_t)rbase*NPG;
    const float* r1p = r0p + NPG;
    float a00=0,a01=0,a10=0,a11=0,d0=0,d1=0;
    #pragma unroll 4
    for (int m = 0; m < NPG; m += 4){
        float4 v0 = *(const float4*)(r0p + m);
        float4 v1 = *(const float4*)(r1p + m);
        float ar0[4] = {v0.x, v0.y, v0.z, v0.w};
        float ar1[4] = {v1.x, v1.y, v1.z, v1.w};
        #pragma unroll
        for (int q = 0; q < 4; q++){
            float u0 = ush[(m+q)*64 + l];
            float u1 = ush[(m+q)*64 + l + 32];
            a00 += ar0[q]*u0; a01 += ar0[q]*u1; d0 += ar0[q];
            a10 += ar1[q]*u0; a11 += ar1[q]*u1; d1 += ar1[q];
        }
    }
    int nb = g*NPG + rbase;
    agg_epi(nb,   a00, a01, d0, tout, dis, l);
    agg_epi(nb+1, a10, a11, d1, tout, dis, l);
}

// ---------------- dense node information score, 2 rows/warp ----------------
template<int NPG>
__global__ void k_scoreT(const float* __restrict__ adj, const float* __restrict__ t,
                         const float* __restrict__ dis, float* __restrict__ score){
    constexpr int TPG = NPG/16;
    __shared__ float tsh[NPG*64];
    int g = blockIdx.x / TPG, rt = blockIdx.x % TPG;
    int w = threadIdx.x >> 5, l = threadIdx.x & 31;
    int rbase = rt*16 + w*2;
    const float* adjg = adj + (size_t)g*NPG*NPG;
    const float* tg   = t   + (size_t)g*NPG*64;
    const float* disg = dis + (size_t)g*NPG;
    {
        const float4* src = (const float4*)tg;
        float4* dst = (float4*)tsh;
        for (int e = threadIdx.x; e < NPG*16; e += 256){
            float4 v = src[e];
            float dm = disg[e >> 4];
            v.x *= dm; v.y *= dm; v.z *= dm; v.w *= dm;
            dst[e] = v;
        }
    }
    float tr0 = tg[(size_t)rbase*64 + l],     tr1 = tg[(size_t)rbase*64 + l + 32];
    float sr0 = tg[(size_t)(rbase+1)*64 + l], sr1 = tg[(size_t)(rbase+1)*64 + l + 32];
    float dr0 = disg[rbase], dr1 = disg[rbase+1];
    __syncthreads();
    const float* r0p = adjg + (size_t)rbase*NPG;
    const float* r1p = r0p + NPG;
    float a00=0,a01=0,a10=0,a11=0;
    #pragma unroll 4
    for (int m = 0; m < NPG; m += 4){
        float4 v0 = *(const float4*)(r0p + m);
        float4 v1 = *(const float4*)(r1p + m);
        float ar0[4] = {v0.x, v0.y, v0.z, v0.w};
        float ar1[4] = {v1.x, v1.y, v1.z, v1.w};
        #pragma unroll
        for (int q = 0; q < 4; q++){
            float u0 = tsh[(m+q)*64 + l];
            float u1 = tsh[(m+q)*64 + l + 32];
            a00 += ar0[q]*u0; a01 += ar0[q]*u1;
            a10 += ar1[q]*u0; a11 += ar1[q]*u1;
        }
    }
    float d0 = fabsf(tr0 - dr0*a00) + fabsf(tr1 - dr0*a01);
    float d1 = fabsf(sr0 - dr1*a10) + fabsf(sr1 - dr1*a11);
    float sc0 = warpSum(d0), sc1 = warpSum(d1);
    if (l == 0){ score[g*NPG + rbase] = sc0; score[g*NPG + rbase + 1] = sc1; }
}

// ---------------- K8: readouts + MLP head + log_softmax ----------------
__global__ void k_final(const float* __restrict__ xn1, const float* __restrict__ xn2,
                        const float* __restrict__ t3,
                        const float* __restrict__ lw1, const float* __restrict__ lb1,
                        const float* __restrict__ lw2, const float* __restrict__ lb2,
                        const float* __restrict__ lw3, const float* __restrict__ lb3,
                        float* __restrict__ out){
    __shared__ float sA[4*64], sB[4*64], rr[128], h1[64], h2[32], lg[NCLS];
    int g = blockIdx.x, t = threadIdx.x;
    int f = t & 63, grp = t >> 6;
    float accM = 0.f, accE = 0.f;
    #pragma unroll
    for (int srci = 0; srci < 3; srci++){
        const float* base = (srci == 0) ? xn1 + (size_t)g*KP1*64
                          : (srci == 1) ? xn2 + (size_t)g*KP2*64
                                        : t3  + (size_t)g*KP2*64;
        int K = (srci == 0) ? KP1 : KP2;
        float pm = -3.402823466e38f, ps = 0.f;
        for (int i = grp; i < K; i += 4){
            float v = base[(size_t)i*64 + f];
            pm = fmaxf(pm, v); ps += v;
        }
        sA[grp*64 + f] = pm; sB[grp*64 + f] = ps;
        __syncthreads();
        if (t < 64){
            float mx = fmaxf(fmaxf(sA[f], sA[64+f]), fmaxf(sA[128+f], sA[192+f]));
            float sm = sB[f] + sB[64+f] + sB[128+f] + sB[192+f];
            accM += fmaxf(mx, 0.f);
            accE += fmaxf(sm/(float)K, 0.f);
        }
        __syncthreads();
    }
    if (t < 64){ rr[f] = accM; rr[64+f] = accE; }
    __syncthreads();
    if (t < 64){
        float a = lb1[t];
        #pragma unroll 8
        for (int q = 0; q < 128; q++) a += lw1[(size_t)t*128 + q]*rr[q];
        h1[t] = fmaxf(a, 0.f);
    }
    __syncthreads();
    if (t < 32){
        float a = lb2[t];
        #pragma unroll 8
        for (int q = 0; q < 64; q++) a += lw2[(size_t)t*64 + q]*h1[q];
        h2[t] = fmaxf(a, 0.f);
    }
    __syncthreads();
    if (t < NCLS){
        float a = lb3[t];
        #pragma unroll
        for (int q = 0; q < 32; q++) a += lw3[(size_t)t*32 + q]*h2[q];
        lg[t] = a;
    }
    __syncthreads();
    if (t == 0){
        float mx = lg[0];
        for (int c = 1; c < NCLS; c++) mx = fmaxf(mx, lg[c]);
        float sm = 0.f;
        for (int c = 0; c < NCLS; c++) sm += expf(lg[c] - mx);
        float lse = mx + logf(sm);
        for (int c = 0; c < NCLS; c++) out[g*NCLS + c] = lg[c] - lse;
    }
}

// ---------------- host launcher ----------------
extern "C" void kernel_launch(void* const* d_in, const int* in_sizes, int n_in,
                              void* d_out, int out_size){
    const float* x    = (const float*)d_in[0];
    const int*   ei   = (const int*)  d_in[1];
    const float* W1   = (const float*)d_in[2];
    const float* b1   = (const float*)d_in[3];
    const float* W2   = (const float*)d_in[4];
    const float* b2   = (const float*)d_in[5];
    const float* W3   = (const float*)d_in[6];
    const float* b3   = (const float*)d_in[7];
    const float* att1 = (const float*)d_in[8];
    const float* att2 = (const float*)d_in[9];
    const float* lw1  = (const float*)d_in[10];
    const float* lb1  = (const float*)d_in[11];
    const float* lw2  = (const float*)d_in[12];
    const float* lb2  = (const float*)d_in[13];
    const float* lw3  = (const float*)d_in[14];
    const float* lb3  = (const float*)d_in[15];
    float* out = (float*)d_out;
    int E = in_sizes[1]/2;

    unsigned* bm; float *s, *u, *t1, *dis, *score, *xn1, *adj2, *t2, *xn2, *adj3, *t3;
    cudaGetSymbolAddress((void**)&bm,    g_bm);
    cudaGetSymbolAddress((void**)&s,     g_s);
    cudaGetSymbolAddress((void**)&u,     g_u);
    cudaGetSymbolAddress((void**)&t1,    g_t1);
    cudaGetSymbolAddress((void**)&dis,   g_dis);
    cudaGetSymbolAddress((void**)&score, g_score);
    cudaGetSymbolAddress((void**)&xn1,   g_xn1);
    cudaGetSymbolAddress((void**)&adj2,  g_adj2);
    cudaGetSymbolAddress((void**)&t2,    g_t2);
    cudaGetSymbolAddress((void**)&xn2,   g_xn2);
    cudaGetSymbolAddress((void**)&adj3,  g_adj3);
    cudaGetSymbolAddress((void**)&t3,    g_t3);

    // layer 1 (sparse; scatter fused into prep1, bitmap pre-zeroed invariant)
    k_prep1   <<<NN1/8, 256>>>(x, W1, b1, ei, E, bm, s, u);
    k_agg1    <<<NN1/8, 256>>>(bm, s, u, t1, dis);
    k_score1  <<<NN1/8, 256>>>(bm, s, t1, dis, score);
    k_topk1   <<<NB, 256>>>(score, t1, att1, bm, s, xn1, adj2);
    // layer 2 (dense 128)
    k_linear  <<<NN2/8, 256>>>(xn1, W2, b2, u);
    k_aggT<KP1>  <<<NB*KP1/16, 256>>>(adj2, u, t2, dis);
    k_scoreT<KP1><<<NB*KP1/16, 256>>>(adj2, t2, dis, score);
    k_topk2   <<<NB, 128>>>(score, t2, att2, adj2, xn2, adj3);
    // layer 3 (dense 64)
    k_linear  <<<NN3/8, 256>>>(xn2, W3, b3, u);
    k_aggT<KP2><<<NB*KP2/16, 256>>>(adj3, u, t3, dis);
    // readout + MLP
    k_final   <<<NB, 256>>>(xn1, xn2, t3, lw1, lb1, lw2, lb2, lw3, lb3, out);
}

// round 10
// speedup vs baseline: 1.1036x; 1.1036x over previous
#include <cuda_runtime.h>
#include <math.h>

#define NB     32
#define NPG1   256
#define NFEATD 128
#define NHID   64
#define KP1    128
#define KP2    64
#define NN1    (NB*NPG1)   // 8192
#define NN2    (NB*KP1)    // 4096
#define NN3    (NB*KP2)    // 2048
#define NCLS   6
#define PROJ_MAX 0.996f
#define MINN   1e-15f
#define AART   3.1063030f   // artanh(0.996)

// ---------------- device scratch ----------------
__device__ unsigned g_bm[NN1*8];        // layer-1 adjacency bitmap (256 bits/row)
__device__ float g_s[NN1];
__device__ float g_u[NN1*NHID];
__device__ float g_t1[NN1*NHID];
__device__ float g_dis[NN1];
__device__ float g_score[NN1];
__device__ int   g_lidx[NB*KP1];
__device__ float g_a1[NB*KP1];
__device__ float g_a2[NB*KP1];
__device__ float g_xn1[NN2*NHID];
__device__ float g_adj2[NB*KP1*KP1];
__device__ float g_t2[NN2*NHID];
__device__ float g_xn2[NN3*NHID];
__device__ float g_adj3[NB*KP2*KP2];
__device__ float g_t3[NN3*NHID];

// ---------------- helpers ----------------
__device__ __forceinline__ float artanh_(float x){
    x = fminf(fmaxf(x, -1.0f + 1e-7f), 1.0f - 1e-7f);
    return 0.5f*(log1pf(x) - log1pf(-x));
}
__device__ __forceinline__ float warpSum(float v){
    #pragma unroll
    for (int o = 16; o; o >>= 1) v += __shfl_xor_sync(0xffffffffu, v, o);
    return v;
}

// mobius tail: u = logmap0(proj(mobius_add(proj(expmap-scaled matvec), hb)))
__device__ __forceinline__ void hyp_tail(float mx0, float mx1, float xn,
                                         const float* __restrict__ bb, int l,
                                         float* __restrict__ up){
    float mxn = fmaxf(sqrtf(warpSum(mx0*mx0 + mx1*mx1)), MINN);
    float tv  = tanhf(mxn/xn*artanh_(xn));
    float hs  = tv/mxn;
    float h0 = mx0*hs, h1 = mx1*hs;
    float hn = tv;
    if (hn > PROJ_MAX){ float c = PROJ_MAX/hn; h0 *= c; h1 *= c; hn = PROJ_MAX; }
    float x2 = hn*hn;
    float b0 = bb[l], b1 = bb[l+32];
    float bn = fmaxf(sqrtf(warpSum(b0*b0 + b1*b1)), MINN);
    float tb = tanhf(bn);
    float hbs = tb/bn, hbn = tb;
    if (tb > PROJ_MAX){ hbs = PROJ_MAX/bn; hbn = PROJ_MAX; }
    float hb0 = b0*hbs, hb1 = b1*hbs;
    float y2 = hbn*hbn;
    float xy = warpSum(h0*hb0 + h1*hb1);
    float ca = 1.f + 2.f*xy + y2, cb = 1.f - x2;
    float den = fmaxf(1.f + 2.f*xy + x2*y2, MINN);
    float r0 = (ca*h0 + cb*hb0)/den, r1 = (ca*h1 + cb*hb1)/den;
    float rn = fmaxf(sqrtf(warpSum(r0*r0 + r1*r1)), MINN);
    float pn = rn, psc = 1.f;
    if (rn > PROJ_MAX){ psc = PROJ_MAX/rn; pn = PROJ_MAX; }
    float ls = artanh_(pn)/pn*psc;
    up[l] = r0*ls; up[l+32] = r1*ls;
}

__device__ __forceinline__ void agg_epi(int node, float a0, float a1, float deg,
                                        float* __restrict__ tout, float* __restrict__ dis, int l){
    float n1 = sqrtf(warpSum(a0*a0 + a1*a1));
    float s1 = (n1 > AART) ? AART/n1 : 1.f;
    float w0 = fmaxf(a0*s1, 0.f), w1 = fmaxf(a1*s1, 0.f);
    float n2 = sqrtf(warpSum(w0*w0 + w1*w1));
    float s2 = (n2 > AART) ? AART/n2 : 1.f;
    tout[(size_t)node*64 + l]      = w0*s2;
    tout[(size_t)node*64 + l + 32] = w1*s2;
    if (l == 0) dis[node] = (deg > 0.f) ? rsqrtf(deg) : 0.f;
}

// ---------------- K1: zero bitmap + row sums + to_hyp + HypLinear (layer1) ----------------
__global__ void k_prep1(const float* __restrict__ x, const float* __restrict__ W1,
                        const float* __restrict__ bb, unsigned* __restrict__ bm,
                        float* __restrict__ s, float* __restrict__ u){
    __shared__ float Wt[128*64];
    int tid = threadIdx.x;
    if (tid < 64) bm[blockIdx.x*64 + tid] = 0u;   // 1024 blocks x 64 = 64K words
    for (int e = tid; e < 128*64; e += 256){
        int j = e >> 7, k = e & 127;
        Wt[k*64 + j] = W1[e];
    }
    __syncthreads();
    int w = tid >> 5, l = tid & 31;
    int node = blockIdx.x*8 + w;
    const float* xp = x + (size_t)node*128;
    float xq[4];
    #pragma unroll
    for (int q = 0; q < 4; q++) xq[q] = xp[l + 32*q];
    float ssum = warpSum(xq[0]+xq[1]+xq[2]+xq[3]);
    if (l == 0) s[node] = ssum;
    float n0 = fmaxf(sqrtf(warpSum(xq[0]*xq[0]+xq[1]*xq[1]+xq[2]*xq[2]+xq[3]*xq[3])), MINN);
    float th = tanhf(n0);
    float xsc, xn;
    if (th > PROJ_MAX){ xsc = PROJ_MAX/n0; xn = PROJ_MAX; } else { xsc = th/n0; xn = th; }
    xn = fmaxf(xn, MINN);
    #pragma unroll
    for (int q = 0; q < 4; q++) xq[q] *= xsc;
    float mx0 = 0.f, mx1 = 0.f;
    #pragma unroll
    for (int q = 0; q < 4; q++){
        float xv = xq[q];
        for (int kk = 0; kk < 32; kk++){
            float xk = __shfl_sync(0xffffffffu, xv, kk);
            int k = q*32 + kk;
            mx0 += xk*Wt[k*64 + l];
            mx1 += xk*Wt[k*64 + l + 32];
        }
    }
    hyp_tail(mx0, mx1, xn, bb, l, u + (size_t)node*64);
}

// ---------------- K2: edge scatter -> bitmap ----------------
__global__ void k_scatter(const int* __restrict__ ei, int E, unsigned* __restrict__ bm){
    int e = blockIdx.x*blockDim.x + threadIdx.x;
    if (e >= E) return;
    int r = ei[e], c = ei[E + e];
    int lc = c & 255;
    atomicOr(&bm[(size_t)r*8 + (lc >> 5)], 1u << (lc & 31));
}

// ---------------- K3: sparse layer-1 HypAgg ----------------
__global__ void k_agg1(const unsigned* __restrict__ bm, const float* __restrict__ s,
                       const float* __restrict__ u, float* __restrict__ tout,
                       float* __restrict__ dis){
    int w = threadIdx.x >> 5, l = threadIdx.x & 31;
    int node = blockIdx.x*8 + w;
    int g = node >> 8;
    const float* ug = u + ((size_t)(g << 8))*64;
    const float* sg = s + (g << 8);
    float sn = sg[node & 255];
    float a0 = 0.f, a1 = 0.f, deg = 0.f;
    #pragma unroll
    for (int w8 = 0; w8 < 8; w8++){
        unsigned bits = bm[(size_t)node*8 + w8];
        while (bits){
            int b = __ffs(bits) - 1; bits &= bits - 1;
            int c = (w8 << 5) | b;
            float wv = 0.5f*(sn + sg[c]);
            a0 += wv*ug[(size_t)c*64 + l];
            a1 += wv*ug[(size_t)c*64 + l + 32];
            deg += wv;
        }
    }
    agg_epi(node, a0, a1, deg, tout, dis, l);
}

// ---------------- K4: sparse layer-1 node information score ----------------
__global__ void k_score1(const unsigned* __restrict__ bm, const float* __restrict__ s,
                         const float* __restrict__ t, const float* __restrict__ dis,
                         float* __restrict__ score){
    int w = threadIdx.x >> 5, l = threadIdx.x & 31;
    int node = blockIdx.x*8 + w;
    int g = node >> 8;
    const float* tg = t + ((size_t)(g << 8))*64;
    const float* sg = s + (g << 8);
    const float* dg = dis + (g << 8);
    float sn = sg[node & 255];
    float dn = dg[node & 255];
    float a0 = 0.f, a1 = 0.f;
    #pragma unroll
    for (int w8 = 0; w8 < 8; w8++){
        unsigned bits = bm[(size_t)node*8 + w8];
        while (bits){
            int b = __ffs(bits) - 1; bits &= bits - 1;
            int c = (w8 << 5) | b;
            float wv = 0.5f*(sn + sg[c])*dg[c];
            a0 += wv*tg[(size_t)c*64 + l];
            a1 += wv*tg[(size_t)c*64 + l + 32];
        }
    }
    float tr0 = tg[(size_t)(node & 255)*64 + l];
    float tr1 = tg[(size_t)(node & 255)*64 + l + 32];
    float d = fabsf(tr0 - dn*a0) + fabsf(tr1 - dn*a1);
    float sc = warpSum(d);
    if (l == 0) score[node] = sc;
}

// ---------------- K5: rank-based top-k selection (no sort, no barriers) ----------------
// rank[t] = #{p : key[p]>key[t] or (key[p]==key[t] and p<t)} == position in stable
// descending sort. Threads with rank<K write their own output row directly.
template<int NPG, int K>
__global__ void k_sel(const float* __restrict__ score, const float* __restrict__ tin,
                      const float* __restrict__ att, int* __restrict__ lidx,
                      float* __restrict__ a1, float* __restrict__ a2,
                      float* __restrict__ xn){
    __shared__ float key[NPG];
    __shared__ float satt[128];
    int g = blockIdx.x, t = threadIdx.x;          // blockDim == NPG
    key[t] = score[g*NPG + t];
    if (t < 128) satt[t] = att[t];
    __syncthreads();
    float kt = key[t];
    int rank = 0;
    #pragma unroll 8
    for (int p = 0; p < NPG; p++){
        float kp = key[p];
        rank += (kp > kt || (kp == kt && p < t)) ? 1 : 0;
    }
    if (rank < K){
        lidx[g*K + rank] = t;
        float tv = tanhf(kt);
        const float* src = tin + ((size_t)g*NPG + t)*64;
        float* dst = xn + ((size_t)g*K + rank)*64;
        float d1 = 0.f, d2 = 0.f;
        #pragma unroll 8
        for (int j = 0; j < 64; j++){
            float v = src[j]*tv; dst[j] = v;
            d1 += v*satt[j]; d2 += v*satt[64 + j];
        }
        a1[g*K + rank] = d1; a2[g*K + rank] = d2;
    }
}

// ---------------- K6a: build adj2 from bitmap (grid NB*KP1 x KP1) ----------------
__global__ void k_adjb1(const int* __restrict__ lidx, const float* __restrict__ a1,
                        const float* __restrict__ a2, const unsigned* __restrict__ bm,
                        const float* __restrict__ s, float* __restrict__ adj2){
    int bi = blockIdx.x;             // g*128 + i
    int g = bi >> 7;
    int j = threadIdx.x;             // 128
    int li = lidx[bi];
    float a1i = a1[bi];
    int lj = lidx[(g << 7) + j];
    float ev = fmaxf(a1i + a2[(g << 7) + j], 0.f);   // relu(leaky_relu) == relu
    unsigned word = bm[((size_t)(g << 8) + li)*8 + (lj >> 5)];
    float old = ((word >> (lj & 31)) & 1u) ? 0.5f*(s[(g << 8) + li] + s[(g << 8) + lj]) : 0.f;
    adj2[(size_t)bi*128 + j] = ev + old;
}

// ---------------- K6b: build adj3 from dense adj2 (grid NB*KP2 x KP2) ----------------
__global__ void k_adjb2(const int* __restrict__ lidx, const float* __restrict__ a1,
                        const float* __restrict__ a2, const float* __restrict__ oldadj,
                        float* __restrict__ adj3){
    int bi = blockIdx.x;             // g*64 + i
    int g = bi >> 6;
    int j = threadIdx.x;             // 64
    int li = lidx[bi];
    float a1i = a1[bi];
    int lj = lidx[(g << 6) + j];
    float ev = fmaxf(a1i + a2[(g << 6) + j], 0.f);
    float old = oldadj[((size_t)(g << 7) + li)*128 + lj];
    adj3[(size_t)bi*64 + j] = ev + old;
}

// ---------------- K7: to_hyp + HypLinear, 64-dim ----------------
__global__ void k_linear(const float* __restrict__ xin, const float* __restrict__ W,
                         const float* __restrict__ bb, float* __restrict__ u){
    __shared__ float Wt[64*64];
    int tid = threadIdx.x;
    for (int e = tid; e < 4096; e += 256){
        int j = e >> 6, k = e & 63;
        Wt[k*64 + j] = W[e];
    }
    __syncthreads();
    int w = tid >> 5, l = tid & 31;
    int node = blockIdx.x*8 + w;
    const float* xp = xin + (size_t)node*64;
    float x0 = xp[l], x1 = xp[l+32];
    float n0 = fmaxf(sqrtf(warpSum(x0*x0 + x1*x1)), MINN);
    float th = tanhf(n0);
    float xsc, xn;
    if (th > PROJ_MAX){ xsc = PROJ_MAX/n0; xn = PROJ_MAX; } else { xsc = th/n0; xn = th; }
    xn = fmaxf(xn, MINN);
    x0 *= xsc; x1 *= xsc;
    float mx0 = 0.f, mx1 = 0.f;
    #pragma unroll
    for (int q = 0; q < 2; q++){
        float xv = q ? x1 : x0;
        for (int kk = 0; kk < 32; kk++){
            float xk = __shfl_sync(0xffffffffu, xv, kk);
            int k = q*32 + kk;
            mx0 += xk*Wt[k*64 + l];
            mx1 += xk*Wt[k*64 + l + 32];
        }
    }
    hyp_tail(mx0, mx1, xn, bb, l, u + (size_t)node*64);
}

// ---------------- dense HypAgg, 2 rows/warp ----------------
template<int NPG>
__global__ void k_aggT(const float* __restrict__ adj, const float* __restrict__ u,
                       float* __restrict__ tout, float* __restrict__ dis){
    constexpr int TPG = NPG/16;
    __shared__ float ush[NPG*64];
    int g = blockIdx.x / TPG, rt = blockIdx.x % TPG;
    int w = threadIdx.x >> 5, l = threadIdx.x & 31;
    int rbase = rt*16 + w*2;
    const float* adjg = adj + (size_t)g*NPG*NPG;
    const float* ug   = u   + (size_t)g*NPG*64;
    {
        const float4* src = (const float4*)ug;
        float4* dst = (float4*)ush;
        for (int e = threadIdx.x; e < NPG*16; e += 256) dst[e] = src[e];
    }
    __syncthreads();
    const float* r0p = adjg + (size_t)rbase*NPG;
    const float* r1p = r0p + NPG;
    float a00=0,a01=0,a10=0,a11=0,d0=0,d1=0;
    #pragma unroll 4
    for (int m = 0; m < NPG; m += 4){
        float4 v0 = *(const float4*)(r0p + m);
        float4 v1 = *(const float4*)(r1p + m);
        float ar0[4] = {v0.x, v0.y, v0.z, v0.w};
        float ar1[4] = {v1.x, v1.y, v1.z, v1.w};
        #pragma unroll
        for (int q = 0; q < 4; q++){
            float u0 = ush[(m+q)*64 + l];
            float u1 = ush[(m+q)*64 + l + 32];
            a00 += ar0[q]*u0; a01 += ar0[q]*u1; d0 += ar0[q];
            a10 += ar1[q]*u0; a11 += ar1[q]*u1; d1 += ar1[q];
        }
    }
    int nb = g*NPG + rbase;
    agg_epi(nb,   a00, a01, d0, tout, dis, l);
    agg_epi(nb+1, a10, a11, d1, tout, dis, l);
}

// ---------------- dense node information score, 2 rows/warp ----------------
template<int NPG>
__global__ void k_scoreT(const float* __restrict__ adj, const float* __restrict__ t,
                         const float* __restrict__ dis, float* __restrict__ score){
    constexpr int TPG = NPG/16;
    __shared__ float tsh[NPG*64];
    int g = blockIdx.x / TPG, rt = blockIdx.x % TPG;
    int w = threadIdx.x >> 5, l = threadIdx.x & 31;
    int rbase = rt*16 + w*2;
    const float* adjg = adj + (size_t)g*NPG*NPG;
    const float* tg   = t   + (size_t)g*NPG*64;
    const float* disg = dis + (size_t)g*NPG;
    {
        const float4* src = (const float4*)tg;
        float4* dst = (float4*)tsh;
        for (int e = threadIdx.x; e < NPG*16; e += 256){
            float4 v = src[e];
            float dm = disg[e >> 4];
            v.x *= dm; v.y *= dm; v.z *= dm; v.w *= dm;
            dst[e] = v;
        }
    }
    float tr0 = tg[(size_t)rbase*64 + l],     tr1 = tg[(size_t)rbase*64 + l + 32];
    float sr0 = tg[(size_t)(rbase+1)*64 + l], sr1 = tg[(size_t)(rbase+1)*64 + l + 32];
    float dr0 = disg[rbase], dr1 = disg[rbase+1];
    __syncthreads();
    const float* r0p = adjg + (size_t)rbase*NPG;
    const float* r1p = r0p + NPG;
    float a00=0,a01=0,a10=0,a11=0;
    #pragma unroll 4
    for (int m = 0; m < NPG; m += 4){
        float4 v0 = *(const float4*)(r0p + m);
        float4 v1 = *(const float4*)(r1p + m);
        float ar0[4] = {v0.x, v0.y, v0.z, v0.w};
        float ar1[4] = {v1.x, v1.y, v1.z, v1.w};
        #pragma unroll
        for (int q = 0; q < 4; q++){
            float u0 = tsh[(m+q)*64 + l];
            float u1 = tsh[(m+q)*64 + l + 32];
            a00 += ar0[q]*u0; a01 += ar0[q]*u1;
            a10 += ar1[q]*u0; a11 += ar1[q]*u1;
        }
    }
    float d0 = fabsf(tr0 - dr0*a00) + fabsf(tr1 - dr0*a01);
    float d1 = fabsf(sr0 - dr1*a10) + fabsf(sr1 - dr1*a11);
    float sc0 = warpSum(d0), sc1 = warpSum(d1);
    if (l == 0){ score[g*NPG + rbase] = sc0; score[g*NPG + rbase + 1] = sc1; }
}

// ---------------- K8: readouts + MLP head + log_softmax ----------------
__global__ void k_final(const float* __restrict__ xn1, const float* __restrict__ xn2,
                        const float* __restrict__ t3,
                        const float* __restrict__ lw1, const float* __restrict__ lb1,
                        const float* __restrict__ lw2, const float* __restrict__ lb2,
                        const float* __restrict__ lw3, const float* __restrict__ lb3,
                        float* __restrict__ out){
    __shared__ float sA[4*64], sB[4*64], rr[128], h1[64], h2[32], lg[NCLS];
    int g = blockIdx.x, t = threadIdx.x;
    int f = t & 63, grp = t >> 6;
    float accM = 0.f, accE = 0.f;
    #pragma unroll
    for (int srci = 0; srci < 3; srci++){
        const float* base = (srci == 0) ? xn1 + (size_t)g*KP1*64
                          : (srci == 1) ? xn2 + (size_t)g*KP2*64
                                        : t3  + (size_t)g*KP2*64;
        int K = (srci == 0) ? KP1 : KP2;
        float pm = -3.402823466e38f, ps = 0.f;
        for (int i = grp; i < K; i += 4){
            float v = base[(size_t)i*64 + f];
            pm = fmaxf(pm, v); ps += v;
        }
        sA[grp*64 + f] = pm; sB[grp*64 + f] = ps;
        __syncthreads();
        if (t < 64){
            float mx = fmaxf(fmaxf(sA[f], sA[64+f]), fmaxf(sA[128+f], sA[192+f]));
            float sm = sB[f] + sB[64+f] + sB[128+f] + sB[192+f];
            accM += fmaxf(mx, 0.f);
            accE += fmaxf(sm/(float)K, 0.f);
        }
        __syncthreads();
    }
    if (t < 64){ rr[f] = accM; rr[64+f] = accE; }
    __syncthreads();
    if (t < 64){
        float a = lb1[t];
        #pragma unroll 8
        for (int q = 0; q < 128; q++) a += lw1[(size_t)t*128 + q]*rr[q];
        h1[t] = fmaxf(a, 0.f);
    }
    __syncthreads();
    if (t < 32){
        float a = lb2[t];
        #pragma unroll 8
        for (int q = 0; q < 64; q++) a += lw2[(size_t)t*64 + q]*h1[q];
        h2[t] = fmaxf(a, 0.f);
    }
    __syncthreads();
    if (t < NCLS){
        float a = lb3[t];
        #pragma unroll
        for (int q = 0; q < 32; q++) a += lw3[(size_t)t*32 + q]*h2[q];
        lg[t] = a;
    }
    __syncthreads();
    if (t == 0){
        float mx = lg[0];
        for (int c = 1; c < NCLS; c++) mx = fmaxf(mx, lg[c]);
        float sm = 0.f;
        for (int c = 0; c < NCLS; c++) sm += expf(lg[c] - mx);
        float lse = mx + logf(sm);
        for (int c = 0; c < NCLS; c++) out[g*NCLS + c] = lg[c] - lse;
    }
}

// ---------------- host launcher ----------------
extern "C" void kernel_launch(void* const* d_in, const int* in_sizes, int n_in,
                              void* d_out, int out_size){
    const float* x    = (const float*)d_in[0];
    const int*   ei   = (const int*)  d_in[1];
    const float* W1   = (const float*)d_in[2];
    const float* b1   = (const float*)d_in[3];
    const float* W2   = (const float*)d_in[4];
    const float* b2   = (const float*)d_in[5];
    const float* W3   = (const float*)d_in[6];
    const float* b3   = (const float*)d_in[7];
    const float* att1 = (const float*)d_in[8];
    const float* att2 = (const float*)d_in[9];
    const float* lw1  = (const float*)d_in[10];
    const float* lb1  = (const float*)d_in[11];
    const float* lw2  = (const float*)d_in[12];
    const float* lb2  = (const float*)d_in[13];
    const float* lw3  = (const float*)d_in[14];
    const float* lb3  = (const float*)d_in[15];
    float* out = (float*)d_out;
    int E = in_sizes[1]/2;

    unsigned* bm; int* lidx;
    float *s, *u, *t1, *dis, *score, *a1, *a2, *xn1, *adj2, *t2, *xn2, *adj3, *t3;
    cudaGetSymbolAddress((void**)&bm,    g_bm);
    cudaGetSymbolAddress((void**)&s,     g_s);
    cudaGetSymbolAddress((void**)&u,     g_u);
    cudaGetSymbolAddress((void**)&t1,    g_t1);
    cudaGetSymbolAddress((void**)&dis,   g_dis);
    cudaGetSymbolAddress((void**)&score, g_score);
    cudaGetSymbolAddress((void**)&lidx,  g_lidx);
    cudaGetSymbolAddress((void**)&a1,    g_a1);
    cudaGetSymbolAddress((void**)&a2,    g_a2);
    cudaGetSymbolAddress((void**)&xn1,   g_xn1);
    cudaGetSymbolAddress((void**)&adj2,  g_adj2);
    cudaGetSymbolAddress((void**)&t2,    g_t2);
    cudaGetSymbolAddress((void**)&xn2,   g_xn2);
    cudaGetSymbolAddress((void**)&adj3,  g_adj3);
    cudaGetSymbolAddress((void**)&t3,    g_t3);

    // layer 1 (sparse bitmap)
    k_prep1   <<<NN1/8, 256>>>(x, W1, b1, bm, s, u);
    k_scatter <<<(E + 255)/256, 256>>>(ei, E, bm);
    k_agg1    <<<NN1/8, 256>>>(bm, s, u, t1, dis);
    k_score1  <<<NN1/8, 256>>>(bm, s, t1, dis, score);
    k_sel<NPG1,KP1><<<NB, NPG1>>>(score, t1, att1, lidx, a1, a2, xn1);
    k_adjb1   <<<NB*KP1, KP1>>>(lidx, a1, a2, bm, s, adj2);
    // layer 2 (dense 128)
    k_linear  <<<NN2/8, 256>>>(xn1, W2, b2, u);
    k_aggT<KP1>  <<<NB*KP1/16, 256>>>(adj2, u, t2, dis);
    k_scoreT<KP1><<<NB*KP1/16, 256>>>(adj2, t2, dis, score);
    k_sel<KP1,KP2><<<NB, KP1>>>(score, t2, att2, lidx, a1, a2, xn2);
    k_adjb2   <<<NB*KP2, KP2>>>(lidx, a1, a2, adj2, adj3);
    // layer 3 (dense 64)
    k_linear  <<<NN3/8, 256>>>(xn2, W3, b3, u);
    k_aggT<KP2><<<NB*KP2/16, 256>>>(adj3, u, t3, dis);
    // readout + MLP
    k_final   <<<NB, 256>>>(xn1, xn2, t3, lw1, lb1, lw2, lb2, lw3, lb3, out);
}